// round 8
// baseline (speedup 1.0000x reference)
#include <cuda_runtime.h>
#include <cuda_bf16.h>
#include <cstdint>
#include <math.h>

// Problem constants: B=32, S=64, E=256, H=4, D=64
#define NROWS 2048
#define EDIM  256
#define NQKV  768
#define NH    4

// ---------------- scratch (__device__ globals, no allocs) -------------------
__device__ __nv_bfloat16 g_Ahi[NROWS * EDIM], g_Alo[NROWS * EDIM];   // exp(x) split
__device__ __nv_bfloat16 g_Bhi[NQKV * EDIM],  g_Blo[NQKV * EDIM];    // exp(Wqkv) [n][k]
__device__ __nv_bfloat16 g_Chi[EDIM * EDIM],  g_Clo[EDIM * EDIM];    // exp(Wo)   [n][k]
__device__ __nv_bfloat16 g_EOhi[NROWS * EDIM], g_EOlo[NROWS * EDIM]; // exp(attn out)
__device__ float g_Y[NROWS * NQKV];  // q,k: sum*exp(bias); v: log(sum)+bv

// ---------------- helpers (base ISA only — sm_103 non-variant) --------------
__device__ __forceinline__ uint32_t smem_u32(const void* p) {
    uint32_t a;
    asm("{ .reg .u64 t; cvta.to.shared.u64 t, %1; cvt.u32.u64 %0, t; }"
        : "=r"(a) : "l"(p));
    return a;
}
__device__ __forceinline__ void ldsm_x4(uint32_t* r, uint32_t addr) {
    asm volatile("ldmatrix.sync.aligned.m8n8.x4.shared.b16 {%0,%1,%2,%3}, [%4];"
                 : "=r"(r[0]), "=r"(r[1]), "=r"(r[2]), "=r"(r[3]) : "r"(addr));
}
__device__ __forceinline__ void mma16816(float* d, const uint32_t* a,
                                         uint32_t b0, uint32_t b1) {
    asm volatile(
        "mma.sync.aligned.m16n8k16.row.col.f32.bf16.bf16.f32 "
        "{%0,%1,%2,%3}, {%4,%5,%6,%7}, {%8,%9}, {%0,%1,%2,%3};"
        : "+f"(d[0]), "+f"(d[1]), "+f"(d[2]), "+f"(d[3])
        : "r"(a[0]), "r"(a[1]), "r"(a[2]), "r"(a[3]), "r"(b0), "r"(b1));
}
__device__ __forceinline__ void cp16(uint32_t s, const void* g) {
    asm volatile("cp.async.cg.shared.global [%0], [%1], 16;" :: "r"(s), "l"(g));
}
#define CP_COMMIT() asm volatile("cp.async.commit_group;" ::: "memory")
#define CP_WAIT1()  asm volatile("cp.async.wait_group 1;" ::: "memory")
#define CP_WAIT0()  asm volatile("cp.async.wait_group 0;" ::: "memory")

// ---------------------------------------------------------------------------
// Prep: exp() everything once, split into bf16 hi/lo pairs. float4-vectorized.
// ---------------------------------------------------------------------------
__global__ void k_prep(const float* __restrict__ x,
                       const float* __restrict__ Wq, const float* __restrict__ Wk,
                       const float* __restrict__ Wv, const float* __restrict__ Wo)
{
    int q = blockIdx.x * blockDim.x + threadIdx.x;   // quad index
    const float* src; __nv_bfloat16 *hi, *lo; int idx;
    if (q < (NROWS * EDIM) / 4) {
        idx = q * 4; src = &x[idx]; hi = g_Ahi; lo = g_Alo;
    } else if (q < (NROWS * EDIM + NQKV * EDIM) / 4) {
        idx = q * 4 - NROWS * EDIM;
        int n = idx / EDIM, k = idx - n * EDIM;
        const float* W = (n < 256) ? Wq : ((n < 512) ? Wk : Wv);
        src = &W[(n & 255) * EDIM + k]; hi = g_Bhi; lo = g_Blo;
    } else {
        idx = q * 4 - NROWS * EDIM - NQKV * EDIM;
        src = &Wo[idx]; hi = g_Chi; lo = g_Clo;
    }
    float4 v4 = *(const float4*)src;
    __nv_bfloat16 h[4], l[4];
    float vv[4] = {__expf(v4.x), __expf(v4.y), __expf(v4.z), __expf(v4.w)};
    #pragma unroll
    for (int j = 0; j < 4; ++j) {
        h[j] = __float2bfloat16(vv[j]);
        l[j] = __float2bfloat16(vv[j] - __bfloat162float(h[j]));
    }
    *(uint2*)&hi[idx] = *(uint2*)h;
    *(uint2*)&lo[idx] = *(uint2*)l;
}

// ---------------------------------------------------------------------------
// bf16x3 GEMM via mma.sync, cp.async double-buffered, 256 threads.
//   C[m,n] = sum_k A[m,k]*B[n,k], fp32 accum. CTA 32x64, warp tile 16x16.
//   4 CTAs/SM co-resident (55.3 KB smem) -> latency hiding via occupancy.
//   mode 0 epilogue: n<256 -> acc*exp(bq), n<512 -> acc*exp(bk), else log+bv
//   mode 1 epilogue: log(acc)+bo
// ---------------------------------------------------------------------------
#define LDT 72                          // padded row stride (bf16), 144 B
#define ARR_A (32 * LDT * 2)            // 4608 B per A array
#define ARR_B (64 * LDT * 2)            // 9216 B per B array
#define OFF_AHI 0
#define OFF_ALO (ARR_A)
#define OFF_BHI (2 * ARR_A)
#define OFF_BLO (2 * ARR_A + ARR_B)
#define STG_BYTES (2 * ARR_A + 2 * ARR_B)   // 27648 per stage
#define SM_TOT    (2 * STG_BYTES)            // 55296

__global__ void __launch_bounds__(256) k_tgemm(
    const __nv_bfloat16* __restrict__ Ahi, const __nv_bfloat16* __restrict__ Alo,
    const __nv_bfloat16* __restrict__ Bhi, const __nv_bfloat16* __restrict__ Blo,
    float* __restrict__ C, int ldc,
    const float* __restrict__ b0, const float* __restrict__ b1,
    const float* __restrict__ b2, int mode)
{
    extern __shared__ char smem[];
    const uint32_t sbase = smem_u32(smem);

    const int tid  = threadIdx.x;
    const int lane = tid & 31;
    const int warp = tid >> 5;
    const int wm   = (warp & 1) * 16;    // warp row offset (2 m-warps)
    const int wn   = (warp >> 1) * 16;   // warp col offset (4 n-warps)
    const int m0 = blockIdx.y * 32;
    const int n0 = blockIdx.x * 64;

    // ldmatrix base byte-offsets within an array
    const uint32_t aOff = (uint32_t)(((wm + (lane & 15)) * LDT + (lane >> 4) * 8) * 2);
    const uint32_t bOff = (uint32_t)(((wn + (lane >> 4) * 8 + (lane & 7)) * LDT
                                      + ((lane >> 3) & 1) * 8) * 2);

    float acc[2][4];
    #pragma unroll
    for (int nf = 0; nf < 2; ++nf)
        #pragma unroll
        for (int j = 0; j < 4; ++j) acc[nf][j] = 0.f;

    // per-thread fill: A = 256 chunks16 (1/thread/array), B = 512 (2/thread/array)
    auto prefetch = [&](int kc, int stg) {
        const int kb = kc * 64;
        const uint32_t s0 = sbase + stg * STG_BYTES;
        {
            int r = tid >> 3, k8 = (tid & 7) * 8;
            uint32_t so = (r * LDT + k8) * 2;
            cp16(s0 + OFF_AHI + so, &Ahi[(m0 + r) * EDIM + kb + k8]);
            cp16(s0 + OFF_ALO + so, &Alo[(m0 + r) * EDIM + kb + k8]);
        }
        #pragma unroll
        for (int i = 0; i < 2; ++i) {
            int c = tid + 256 * i;
            int r = c >> 3, k8 = (c & 7) * 8;
            uint32_t so = (r * LDT + k8) * 2;
            cp16(s0 + OFF_BHI + so, &Bhi[(n0 + r) * EDIM + kb + k8]);
            cp16(s0 + OFF_BLO + so, &Blo[(n0 + r) * EDIM + kb + k8]);
        }
        CP_COMMIT();
    };

    prefetch(0, 0);

    for (int kc = 0; kc < 4; ++kc) {
        if (kc < 3) prefetch(kc + 1, (kc + 1) & 1);
        if (kc < 3) CP_WAIT1(); else CP_WAIT0();
        __syncthreads();

        const uint32_t s0 = sbase + (kc & 1) * STG_BYTES;
        #pragma unroll
        for (int ks = 0; ks < 4; ++ks) {
            const uint32_t kByte = ks * 32;  // 16 bf16
            uint32_t ah[4], al[4], bh[4], bl[4];
            ldsm_x4(ah, s0 + OFF_AHI + aOff + kByte);
            ldsm_x4(al, s0 + OFF_ALO + aOff + kByte);
            ldsm_x4(bh, s0 + OFF_BHI + bOff + kByte);
            ldsm_x4(bl, s0 + OFF_BLO + bOff + kByte);
            #pragma unroll
            for (int nf = 0; nf < 2; ++nf) {
                mma16816(acc[nf], ah, bh[nf * 2], bh[nf * 2 + 1]); // hi*hi
                mma16816(acc[nf], ah, bl[nf * 2], bl[nf * 2 + 1]); // hi*lo
                mma16816(acc[nf], al, bh[nf * 2], bh[nf * 2 + 1]); // lo*hi
            }
        }
        __syncthreads();
    }

    // ---- epilogue ---------------------------------------------------------
    const int l4 = lane >> 2;
    const int l2 = (lane & 3) * 2;
    const int region = n0 >> 8;  // mode 0: 0=q, 1=k, 2=v
    #pragma unroll
    for (int nf = 0; nf < 2; ++nf) {
        int gr = m0 + wm + l4;
        int gc = n0 + wn + nf * 8 + l2;
        float r[4];
        #pragma unroll
        for (int j = 0; j < 4; ++j) {
            float v = acc[nf][j];
            int col = gc + (j & 1);
            if (mode == 0) {
                if (region == 0)      r[j] = v * __expf(b0[col]);
                else if (region == 1) r[j] = v * __expf(b1[col - 256]);
                else                  r[j] = __logf(v) + b2[col - 512];
            } else {
                r[j] = __logf(v) + b0[col];
            }
        }
        *(float2*)&C[gr * ldc + gc]       = make_float2(r[0], r[1]);
        *(float2*)&C[(gr + 8) * ldc + gc] = make_float2(r[2], r[3]);
    }
}

// ---------------------------------------------------------------------------
// Attention: one CTA per (b, h). p = exp(q)*exp(k); attn = p/rowsum;
// out = attn @ v (v = log(Sv)+bv already in g_Y); emit exp(out) as bf16 hi/lo.
// ---------------------------------------------------------------------------
__global__ void k_attn()
{
    __shared__ float P[64][65];
    __shared__ float V[64][68];
    __shared__ float inv[64];

    const int h = blockIdx.x;
    const int b = blockIdx.y;
    const int tid = threadIdx.x;

    for (int i = tid; i < 4096; i += 256) {
        int s = i >> 6, d = i & 63;
        const float* yr = &g_Y[(b * 64 + s) * NQKV + h * 64 + d];
        P[s][d] = yr[0] * yr[256];
    }
    for (int i = tid; i < 4096; i += 256) {
        int d = i >> 6, e = i & 63;
        V[d][e] = g_Y[(b * 64 + d) * NQKV + 512 + h * 64 + e];
    }
    __syncthreads();

    if (tid < 64) {
        float s = 0.f;
        #pragma unroll
        for (int j = 0; j < 64; ++j) s += P[tid][j];
        inv[tid] = 1.0f / s;
    }
    __syncthreads();

    const int tx = tid & 15;
    const int ty = tid >> 4;
    float acc[4][4] = {};

    #pragma unroll 4
    for (int d = 0; d < 64; ++d) {
        float p0 = P[4 * ty + 0][d];
        float p1 = P[4 * ty + 1][d];
        float p2 = P[4 * ty + 2][d];
        float p3 = P[4 * ty + 3][d];
        float4 v4 = *(const float4*)&V[d][4 * tx];
        acc[0][0] += p0 * v4.x; acc[0][1] += p0 * v4.y;
        acc[0][2] += p0 * v4.z; acc[0][3] += p0 * v4.w;
        acc[1][0] += p1 * v4.x; acc[1][1] += p1 * v4.y;
        acc[1][2] += p1 * v4.z; acc[1][3] += p1 * v4.w;
        acc[2][0] += p2 * v4.x; acc[2][1] += p2 * v4.y;
        acc[2][2] += p2 * v4.z; acc[2][3] += p2 * v4.w;
        acc[3][0] += p3 * v4.x; acc[3][1] += p3 * v4.y;
        acc[3][2] += p3 * v4.z; acc[3][3] += p3 * v4.w;
    }

    #pragma unroll
    for (int r = 0; r < 4; ++r) {
        float iv = inv[4 * ty + r];
        int grow = b * 64 + 4 * ty + r;
        #pragma unroll
        for (int c = 0; c < 4; ++c) {
            float eo = __expf(acc[r][c] * iv);
            __nv_bfloat16 hb = __float2bfloat16(eo);
            int gi = grow * EDIM + h * 64 + 4 * tx + c;
            g_EOhi[gi] = hb;
            g_EOlo[gi] = __float2bfloat16(eo - __bfloat162float(hb));
        }
    }
}

// ---------------------------------------------------------------------------
extern "C" void kernel_launch(void* const* d_in, const int* in_sizes, int n_in,
                              void* d_out, int out_size)
{
    const float* x  = (const float*)d_in[0];
    const float* Wq = (const float*)d_in[1];
    const float* bq = (const float*)d_in[2];
    const float* Wk = (const float*)d_in[3];
    const float* bk = (const float*)d_in[4];
    const float* Wv = (const float*)d_in[5];
    const float* bv = (const float*)d_in[6];
    const float* Wo = (const float*)d_in[7];
    const float* bo = (const float*)d_in[8];
    float* out = (float*)d_out;

    static bool attr_set = false;
    if (!attr_set) {
        cudaFuncSetAttribute(k_tgemm, cudaFuncAttributeMaxDynamicSharedMemorySize, SM_TOT);
        attr_set = true;
    }

    float* Y = nullptr; cudaGetSymbolAddress((void**)&Y, g_Y);
    __nv_bfloat16 *Ahi, *Alo, *Bhi, *Blo, *Chi, *Clo, *EOhi, *EOlo;
    cudaGetSymbolAddress((void**)&Ahi, g_Ahi);
    cudaGetSymbolAddress((void**)&Alo, g_Alo);
    cudaGetSymbolAddress((void**)&Bhi, g_Bhi);
    cudaGetSymbolAddress((void**)&Blo, g_Blo);
    cudaGetSymbolAddress((void**)&Chi, g_Chi);
    cudaGetSymbolAddress((void**)&Clo, g_Clo);
    cudaGetSymbolAddress((void**)&EOhi, g_EOhi);
    cudaGetSymbolAddress((void**)&EOlo, g_EOlo);

    // 1. exp + bf16 hi/lo split of all operands, once
    k_prep<<<768, 256>>>(x, Wq, Wk, Wv, Wo);

    // 2. fused QKV GEMM (768 CTAs, 32x64 tiles)
    {
        dim3 grid(NQKV / 64, NROWS / 32);  // (12, 64)
        k_tgemm<<<grid, 256, SM_TOT>>>(Ahi, Alo, Bhi, Blo, Y, NQKV, bq, bk, bv, 0);
    }

    // 3. attention per (b, h)
    {
        dim3 grid(NH, 32);
        k_attn<<<grid, 256>>>();
    }

    // 4. output projection (256 CTAs): out = log(EO @ exp(Wo)) + bo
    {
        dim3 grid(EDIM / 64, NROWS / 32);  // (4, 64)
        k_tgemm<<<grid, 256, SM_TOT>>>(EOhi, EOlo, Chi, Clo, out, EDIM, bo, nullptr, nullptr, 1);
    }
}

// round 9
// speedup vs baseline: 1.0355x; 1.0355x over previous
#include <cuda_runtime.h>
#include <cuda_bf16.h>
#include <cstdint>
#include <math.h>

// Problem constants: B=32, S=64, E=256, H=4, D=64
#define NROWS 2048
#define EDIM  256
#define NQKV  768
#define NH    4

// ---------------- scratch (__device__ globals, no allocs) -------------------
__device__ __nv_bfloat16 g_Ahi[NROWS * EDIM], g_Alo[NROWS * EDIM];   // exp(x) split
__device__ __nv_bfloat16 g_Bhi[NQKV * EDIM],  g_Blo[NQKV * EDIM];    // exp(Wqkv) [n][k]
__device__ __nv_bfloat16 g_Chi[EDIM * EDIM],  g_Clo[EDIM * EDIM];    // exp(Wo)   [n][k]
__device__ __nv_bfloat16 g_EOhi[NROWS * EDIM], g_EOlo[NROWS * EDIM]; // exp(attn out)
__device__ float g_Y[NROWS * NQKV];  // q,k: sum*exp(bias); v: log(sum)+bv

// ---------------- helpers (base ISA only — sm_103 non-variant) --------------
__device__ __forceinline__ uint32_t smem_u32(const void* p) {
    uint32_t a;
    asm("{ .reg .u64 t; cvta.to.shared.u64 t, %1; cvt.u32.u64 %0, t; }"
        : "=r"(a) : "l"(p));
    return a;
}
__device__ __forceinline__ void ldsm_x4(uint32_t* r, uint32_t addr) {
    asm volatile("ldmatrix.sync.aligned.m8n8.x4.shared.b16 {%0,%1,%2,%3}, [%4];"
                 : "=r"(r[0]), "=r"(r[1]), "=r"(r[2]), "=r"(r[3]) : "r"(addr));
}
__device__ __forceinline__ void mma16816(float* d, const uint32_t* a,
                                         uint32_t b0, uint32_t b1) {
    asm volatile(
        "mma.sync.aligned.m16n8k16.row.col.f32.bf16.bf16.f32 "
        "{%0,%1,%2,%3}, {%4,%5,%6,%7}, {%8,%9}, {%0,%1,%2,%3};"
        : "+f"(d[0]), "+f"(d[1]), "+f"(d[2]), "+f"(d[3])
        : "r"(a[0]), "r"(a[1]), "r"(a[2]), "r"(a[3]), "r"(b0), "r"(b1));
}
__device__ __forceinline__ void cp16(uint32_t s, const void* g) {
    asm volatile("cp.async.cg.shared.global [%0], [%1], 16;" :: "r"(s), "l"(g));
}
#define CP_COMMIT() asm volatile("cp.async.commit_group;" ::: "memory")
#define CP_WAIT1()  asm volatile("cp.async.wait_group 1;" ::: "memory")
#define CP_WAIT0()  asm volatile("cp.async.wait_group 0;" ::: "memory")

// ---------------------------------------------------------------------------
// Prep: exp() everything once, split into bf16 hi/lo pairs. float4-vectorized.
// ---------------------------------------------------------------------------
__global__ void k_prep(const float* __restrict__ x,
                       const float* __restrict__ Wq, const float* __restrict__ Wk,
                       const float* __restrict__ Wv, const float* __restrict__ Wo)
{
    int q = blockIdx.x * blockDim.x + threadIdx.x;   // quad index
    const float* src; __nv_bfloat16 *hi, *lo; int idx;
    if (q < (NROWS * EDIM) / 4) {
        idx = q * 4; src = &x[idx]; hi = g_Ahi; lo = g_Alo;
    } else if (q < (NROWS * EDIM + NQKV * EDIM) / 4) {
        idx = q * 4 - NROWS * EDIM;
        int n = idx / EDIM, k = idx - n * EDIM;
        const float* W = (n < 256) ? Wq : ((n < 512) ? Wk : Wv);
        src = &W[(n & 255) * EDIM + k]; hi = g_Bhi; lo = g_Blo;
    } else {
        idx = q * 4 - NROWS * EDIM - NQKV * EDIM;
        src = &Wo[idx]; hi = g_Chi; lo = g_Clo;
    }
    float4 v4 = *(const float4*)src;
    __nv_bfloat16 h[4], l[4];
    float vv[4] = {__expf(v4.x), __expf(v4.y), __expf(v4.z), __expf(v4.w)};
    #pragma unroll
    for (int j = 0; j < 4; ++j) {
        h[j] = __float2bfloat16(vv[j]);
        l[j] = __float2bfloat16(vv[j] - __bfloat162float(h[j]));
    }
    *(uint2*)&hi[idx] = *(uint2*)h;
    *(uint2*)&lo[idx] = *(uint2*)l;
}

// ---------------------------------------------------------------------------
// bf16x3 GEMM via mma.sync, cp.async 3-stage pipeline (prefetch distance 2).
//   C[m,n] = sum_k A[m,k]*B[n,k], fp32 accum. CTA 64x64, 256 thr, warp 32x16.
//   One barrier per K-chunk: wait -> sync -> prefetch(kc+2) -> compute.
//   mode 0 epilogue: n<256 -> acc*exp(bq), n<512 -> acc*exp(bk), else log+bv
//   mode 1 epilogue: log(acc)+bo
// ---------------------------------------------------------------------------
#define LDT 72                         // padded row stride (bf16), 144 B
#define ARR_BYTES (64 * LDT * 2)       // 9216 per array
#define STG_BYTES (4 * ARR_BYTES)      // 36864 per stage: Ahi,Alo,Bhi,Blo
#define NSTG 3
#define SM_TOT (NSTG * STG_BYTES)      // 110592

__global__ void __launch_bounds__(256) k_tgemm(
    const __nv_bfloat16* __restrict__ Ahi, const __nv_bfloat16* __restrict__ Alo,
    const __nv_bfloat16* __restrict__ Bhi, const __nv_bfloat16* __restrict__ Blo,
    float* __restrict__ C, int ldc,
    const float* __restrict__ b0, const float* __restrict__ b1,
    const float* __restrict__ b2, int mode)
{
    extern __shared__ char smem[];
    const uint32_t sbase = smem_u32(smem);

    const int tid  = threadIdx.x;
    const int lane = tid & 31;
    const int warp = tid >> 5;
    const int wm   = (warp & 1) * 32;    // warp row offset
    const int wn   = (warp >> 1) * 16;   // warp col offset
    const int m0 = blockIdx.y * 64;
    const int n0 = blockIdx.x * 64;

    // ldmatrix base byte-offsets within an array
    uint32_t aOff[2];
    #pragma unroll
    for (int mf = 0; mf < 2; ++mf)
        aOff[mf] = (uint32_t)(((wm + mf * 16 + (lane & 15)) * LDT + (lane >> 4) * 8) * 2);
    const uint32_t bOff = (uint32_t)(((wn + (lane >> 4) * 8 + (lane & 7)) * LDT
                                      + ((lane >> 3) & 1) * 8) * 2);

    float acc[2][2][4];
    #pragma unroll
    for (int mf = 0; mf < 2; ++mf)
        #pragma unroll
        for (int nf = 0; nf < 2; ++nf)
            #pragma unroll
            for (int j = 0; j < 4; ++j) acc[mf][nf][j] = 0.f;

    // per-thread fill: 512 16B-chunks per array, 2 per thread
    auto prefetch = [&](int kc) {
        const int kb = kc * 64;
        const uint32_t s0 = sbase + (kc % NSTG) * STG_BYTES;
        #pragma unroll
        for (int i = 0; i < 2; ++i) {
            int c = tid + 256 * i;
            int r = c >> 3, k8 = (c & 7) * 8;
            uint32_t so = (r * LDT + k8) * 2;
            cp16(s0 + 0 * ARR_BYTES + so, &Ahi[(m0 + r) * EDIM + kb + k8]);
            cp16(s0 + 1 * ARR_BYTES + so, &Alo[(m0 + r) * EDIM + kb + k8]);
            cp16(s0 + 2 * ARR_BYTES + so, &Bhi[(n0 + r) * EDIM + kb + k8]);
            cp16(s0 + 3 * ARR_BYTES + so, &Blo[(n0 + r) * EDIM + kb + k8]);
        }
        CP_COMMIT();
    };

    prefetch(0);
    prefetch(1);

    for (int kc = 0; kc < 4; ++kc) {
        // chunk kc was committed >= 2 iterations of compute ago -> wait is cheap
        if (kc < 3) CP_WAIT1(); else CP_WAIT0();
        __syncthreads();                 // publish chunk kc; frees buffer (kc+2)%3
        if (kc < 2) prefetch(kc + 2);

        const uint32_t s0 = sbase + (kc % NSTG) * STG_BYTES;
        #pragma unroll
        for (int ks = 0; ks < 4; ++ks) {
            const uint32_t kByte = ks * 32;  // 16 bf16
            uint32_t ah[2][4], al[2][4], bh[4], bl[4];
            #pragma unroll
            for (int mf = 0; mf < 2; ++mf) {
                ldsm_x4(ah[mf], s0 + 0 * ARR_BYTES + aOff[mf] + kByte);
                ldsm_x4(al[mf], s0 + 1 * ARR_BYTES + aOff[mf] + kByte);
            }
            ldsm_x4(bh, s0 + 2 * ARR_BYTES + bOff + kByte);
            ldsm_x4(bl, s0 + 3 * ARR_BYTES + bOff + kByte);
            #pragma unroll
            for (int mf = 0; mf < 2; ++mf) {
                #pragma unroll
                for (int nf = 0; nf < 2; ++nf) {
                    mma16816(acc[mf][nf], ah[mf], bh[nf * 2], bh[nf * 2 + 1]); // hi*hi
                    mma16816(acc[mf][nf], ah[mf], bl[nf * 2], bl[nf * 2 + 1]); // hi*lo
                    mma16816(acc[mf][nf], al[mf], bh[nf * 2], bh[nf * 2 + 1]); // lo*hi
                }
            }
        }
    }

    // ---- epilogue ---------------------------------------------------------
    const int l4 = lane >> 2;
    const int l2 = (lane & 3) * 2;
    const int region = n0 >> 8;  // mode 0: 0=q, 1=k, 2=v
    #pragma unroll
    for (int mf = 0; mf < 2; ++mf) {
        #pragma unroll
        for (int nf = 0; nf < 2; ++nf) {
            int gr = m0 + wm + mf * 16 + l4;
            int gc = n0 + wn + nf * 8 + l2;
            float r[4];
            #pragma unroll
            for (int j = 0; j < 4; ++j) {
                float v = acc[mf][nf][j];
                int col = gc + (j & 1);
                if (mode == 0) {
                    if (region == 0)      r[j] = v * __expf(b0[col]);
                    else if (region == 1) r[j] = v * __expf(b1[col - 256]);
                    else                  r[j] = __logf(v) + b2[col - 512];
                } else {
                    r[j] = __logf(v) + b0[col];
                }
            }
            *(float2*)&C[gr * ldc + gc]       = make_float2(r[0], r[1]);
            *(float2*)&C[(gr + 8) * ldc + gc] = make_float2(r[2], r[3]);
        }
    }
}

// ---------------------------------------------------------------------------
// Attention: one CTA per (b, h). p = exp(q)*exp(k); attn = p/rowsum;
// out = attn @ v (v = log(Sv)+bv already in g_Y); emit exp(out) as bf16 hi/lo.
// ---------------------------------------------------------------------------
__global__ void k_attn()
{
    __shared__ float P[64][65];
    __shared__ float V[64][68];
    __shared__ float inv[64];

    const int h = blockIdx.x;
    const int b = blockIdx.y;
    const int tid = threadIdx.x;

    for (int i = tid; i < 4096; i += 256) {
        int s = i >> 6, d = i & 63;
        const float* yr = &g_Y[(b * 64 + s) * NQKV + h * 64 + d];
        P[s][d] = yr[0] * yr[256];
    }
    for (int i = tid; i < 4096; i += 256) {
        int d = i >> 6, e = i & 63;
        V[d][e] = g_Y[(b * 64 + d) * NQKV + 512 + h * 64 + e];
    }
    __syncthreads();

    if (tid < 64) {
        float s = 0.f;
        #pragma unroll
        for (int j = 0; j < 64; ++j) s += P[tid][j];
        inv[tid] = 1.0f / s;
    }
    __syncthreads();

    const int tx = tid & 15;
    const int ty = tid >> 4;
    float acc[4][4] = {};

    #pragma unroll 4
    for (int d = 0; d < 64; ++d) {
        float p0 = P[4 * ty + 0][d];
        float p1 = P[4 * ty + 1][d];
        float p2 = P[4 * ty + 2][d];
        float p3 = P[4 * ty + 3][d];
        float4 v4 = *(const float4*)&V[d][4 * tx];
        acc[0][0] += p0 * v4.x; acc[0][1] += p0 * v4.y;
        acc[0][2] += p0 * v4.z; acc[0][3] += p0 * v4.w;
        acc[1][0] += p1 * v4.x; acc[1][1] += p1 * v4.y;
        acc[1][2] += p1 * v4.z; acc[1][3] += p1 * v4.w;
        acc[2][0] += p2 * v4.x; acc[2][1] += p2 * v4.y;
        acc[2][2] += p2 * v4.z; acc[2][3] += p2 * v4.w;
        acc[3][0] += p3 * v4.x; acc[3][1] += p3 * v4.y;
        acc[3][2] += p3 * v4.z; acc[3][3] += p3 * v4.w;
    }

    #pragma unroll
    for (int r = 0; r < 4; ++r) {
        float iv = inv[4 * ty + r];
        int grow = b * 64 + 4 * ty + r;
        #pragma unroll
        for (int c = 0; c < 4; ++c) {
            float eo = __expf(acc[r][c] * iv);
            __nv_bfloat16 hb = __float2bfloat16(eo);
            int gi = grow * EDIM + h * 64 + 4 * tx + c;
            g_EOhi[gi] = hb;
            g_EOlo[gi] = __float2bfloat16(eo - __bfloat162float(hb));
        }
    }
}

// ---------------------------------------------------------------------------
extern "C" void kernel_launch(void* const* d_in, const int* in_sizes, int n_in,
                              void* d_out, int out_size)
{
    const float* x  = (const float*)d_in[0];
    const float* Wq = (const float*)d_in[1];
    const float* bq = (const float*)d_in[2];
    const float* Wk = (const float*)d_in[3];
    const float* bk = (const float*)d_in[4];
    const float* Wv = (const float*)d_in[5];
    const float* bv = (const float*)d_in[6];
    const float* Wo = (const float*)d_in[7];
    const float* bo = (const float*)d_in[8];
    float* out = (float*)d_out;

    static bool attr_set = false;
    if (!attr_set) {
        cudaFuncSetAttribute(k_tgemm, cudaFuncAttributeMaxDynamicSharedMemorySize, SM_TOT);
        attr_set = true;
    }

    float* Y = nullptr; cudaGetSymbolAddress((void**)&Y, g_Y);
    __nv_bfloat16 *Ahi, *Alo, *Bhi, *Blo, *Chi, *Clo, *EOhi, *EOlo;
    cudaGetSymbolAddress((void**)&Ahi, g_Ahi);
    cudaGetSymbolAddress((void**)&Alo, g_Alo);
    cudaGetSymbolAddress((void**)&Bhi, g_Bhi);
    cudaGetSymbolAddress((void**)&Blo, g_Blo);
    cudaGetSymbolAddress((void**)&Chi, g_Chi);
    cudaGetSymbolAddress((void**)&Clo, g_Clo);
    cudaGetSymbolAddress((void**)&EOhi, g_EOhi);
    cudaGetSymbolAddress((void**)&EOlo, g_EOlo);

    // 1. exp + bf16 hi/lo split of all operands, once
    k_prep<<<768, 256>>>(x, Wq, Wk, Wv, Wo);

    // 2. fused QKV GEMM (384 CTAs, 64x64 tiles)
    {
        dim3 grid(NQKV / 64, NROWS / 64);  // (12, 32)
        k_tgemm<<<grid, 256, SM_TOT>>>(Ahi, Alo, Bhi, Blo, Y, NQKV, bq, bk, bv, 0);
    }

    // 3. attention per (b, h)
    {
        dim3 grid(NH, 32);
        k_attn<<<grid, 256>>>();
    }

    // 4. output projection (128 CTAs): out = log(EO @ exp(Wo)) + bo
    {
        dim3 grid(EDIM / 64, NROWS / 64);  // (4, 32)
        k_tgemm<<<grid, 256, SM_TOT>>>(EOhi, EOlo, Chi, Clo, out, EDIM, bo, nullptr, nullptr, 1);
    }
}

// round 10
// speedup vs baseline: 1.4068x; 1.3586x over previous
#include <cuda_runtime.h>
#include <cuda_bf16.h>
#include <cstdint>
#include <math.h>

// Problem constants: B=32, S=64, E=256, H=4, D=64
#define NROWS 2048
#define EDIM  256
#define NQKV  768
#define NH    4

// ---------------- scratch (__device__ globals, no allocs) -------------------
__device__ __nv_bfloat16 g_Ahi[NROWS * EDIM], g_Alo[NROWS * EDIM];   // exp(x) split
__device__ __nv_bfloat16 g_Bhi[NQKV * EDIM],  g_Blo[NQKV * EDIM];    // exp(Wqkv) [n][k]
__device__ __nv_bfloat16 g_Chi[EDIM * EDIM],  g_Clo[EDIM * EDIM];    // exp(Wo)   [n][k]
__device__ __nv_bfloat16 g_EOhi[NROWS * EDIM], g_EOlo[NROWS * EDIM]; // exp(attn out)

// ---------------- helpers (base ISA only — sm_103 non-variant) --------------
__device__ __forceinline__ uint32_t smem_u32(const void* p) {
    uint32_t a;
    asm("{ .reg .u64 t; cvta.to.shared.u64 t, %1; cvt.u32.u64 %0, t; }"
        : "=r"(a) : "l"(p));
    return a;
}
__device__ __forceinline__ void ldsm_x4(uint32_t* r, uint32_t addr) {
    asm volatile("ldmatrix.sync.aligned.m8n8.x4.shared.b16 {%0,%1,%2,%3}, [%4];"
                 : "=r"(r[0]), "=r"(r[1]), "=r"(r[2]), "=r"(r[3]) : "r"(addr));
}
__device__ __forceinline__ void mma16816(float* d, const uint32_t* a,
                                         uint32_t b0, uint32_t b1) {
    asm volatile(
        "mma.sync.aligned.m16n8k16.row.col.f32.bf16.bf16.f32 "
        "{%0,%1,%2,%3}, {%4,%5,%6,%7}, {%8,%9}, {%0,%1,%2,%3};"
        : "+f"(d[0]), "+f"(d[1]), "+f"(d[2]), "+f"(d[3])
        : "r"(a[0]), "r"(a[1]), "r"(a[2]), "r"(a[3]), "r"(b0), "r"(b1));
}
__device__ __forceinline__ void cp16(uint32_t s, const void* g) {
    asm volatile("cp.async.cg.shared.global [%0], [%1], 16;" :: "r"(s), "l"(g));
}
#define CP_COMMIT() asm volatile("cp.async.commit_group;" ::: "memory")
#define CP_WAIT1()  asm volatile("cp.async.wait_group 1;" ::: "memory")
#define CP_WAIT0()  asm volatile("cp.async.wait_group 0;" ::: "memory")

// ---------------------------------------------------------------------------
// Prep: exp() everything once, split into bf16 hi/lo pairs. float4-vectorized.
// ---------------------------------------------------------------------------
__global__ void k_prep(const float* __restrict__ x,
                       const float* __restrict__ Wq, const float* __restrict__ Wk,
                       const float* __restrict__ Wv, const float* __restrict__ Wo)
{
    int q = blockIdx.x * blockDim.x + threadIdx.x;   // quad index
    const float* src; __nv_bfloat16 *hi, *lo; int idx;
    if (q < (NROWS * EDIM) / 4) {
        idx = q * 4; src = &x[idx]; hi = g_Ahi; lo = g_Alo;
    } else if (q < (NROWS * EDIM + NQKV * EDIM) / 4) {
        idx = q * 4 - NROWS * EDIM;
        int n = idx / EDIM, k = idx - n * EDIM;
        const float* W = (n < 256) ? Wq : ((n < 512) ? Wk : Wv);
        src = &W[(n & 255) * EDIM + k]; hi = g_Bhi; lo = g_Blo;
    } else {
        idx = q * 4 - NROWS * EDIM - NQKV * EDIM;
        src = &Wo[idx]; hi = g_Chi; lo = g_Clo;
    }
    float4 v4 = *(const float4*)src;
    __nv_bfloat16 h[4], l[4];
    float vv[4] = {__expf(v4.x), __expf(v4.y), __expf(v4.z), __expf(v4.w)};
    #pragma unroll
    for (int j = 0; j < 4; ++j) {
        h[j] = __float2bfloat16(vv[j]);
        l[j] = __float2bfloat16(vv[j] - __bfloat162float(h[j]));
    }
    *(uint2*)&hi[idx] = *(uint2*)h;
    *(uint2*)&lo[idx] = *(uint2*)l;
}

// ---------------------------------------------------------------------------
// FUSED QKV GEMM + attention. CTA = (head h, batch b), grid (4, 32).
//   A (64 tokens x 256) hi/lo loaded once to smem.
//   B streamed: 12 chunks (3 regions q,k,v x 4 k-chunks), 3-stage cp.async.
//   q,k fold into P = q*exp(bq) * k*exp(bk) in smem; v -> V = log(acc)+bv.
//   Then rowsum, attn = P/rowsum, out = attn @ V, EO = exp(out) -> bf16 hi/lo.
// ---------------------------------------------------------------------------
#define LDTA 264                           // A row stride (bf16 elems)
#define A_ARR (64 * LDTA * 2)              // 33792 B
#define LDT 72                             // B row stride
#define B_ARR (64 * LDT * 2)               // 9216 B
#define OFF_A0 0
#define OFF_A1 A_ARR
#define OFF_B  (2 * A_ARR)                 // 67584
#define OFF_P  (OFF_B + 6 * B_ARR)         // 67584 + 55296 = 122880
#define OFF_V  (OFF_P + 64 * 65 * 4)       // +16640 = 139520
#define OFF_INV (OFF_V + 64 * 68 * 4)      // +17408 = 156928
#define FUSED_SMEM (OFF_INV + 256)         // 157184

__global__ void __launch_bounds__(256) k_qkv_attn(
    const __nv_bfloat16* __restrict__ Ahi, const __nv_bfloat16* __restrict__ Alo,
    const __nv_bfloat16* __restrict__ Bhi, const __nv_bfloat16* __restrict__ Blo,
    const float* __restrict__ bq, const float* __restrict__ bk,
    const float* __restrict__ bv)
{
    extern __shared__ char smem[];
    const uint32_t sbase = smem_u32(smem);
    float* P   = (float*)(smem + OFF_P);   // [64][65]
    float* V   = (float*)(smem + OFF_V);   // [64][68]
    float* inv = (float*)(smem + OFF_INV);

    const int tid  = threadIdx.x;
    const int lane = tid & 31;
    const int warp = tid >> 5;
    const int wm   = (warp & 1) * 32;
    const int wn   = (warp >> 1) * 16;
    const int h = blockIdx.x;
    const int b = blockIdx.y;
    const int m0 = b * 64;

    // ---- load full A (64 x 256, hi+lo) : 2048 chunks16/array, 8/thread ----
    #pragma unroll
    for (int i = 0; i < 8; ++i) {
        int c = tid + 256 * i;
        int r = c >> 5, k8 = (c & 31) * 8;
        uint32_t so = (r * LDTA + k8) * 2;
        cp16(sbase + OFF_A0 + so, &Ahi[(m0 + r) * EDIM + k8]);
        cp16(sbase + OFF_A1 + so, &Alo[(m0 + r) * EDIM + k8]);
    }
    CP_COMMIT();

    // B prefetch: chunk it (region = it>>2, kc = it&3), stage it%3
    auto prefB = [&](int it) {
        const int reg = it >> 2, kc = it & 3;
        const int brow0 = reg * 256 + h * 64;
        const uint32_t s0 = sbase + OFF_B + (uint32_t)(it % 3) * (2 * B_ARR);
        #pragma unroll
        for (int i = 0; i < 2; ++i) {
            int c = tid + 256 * i;
            int r = c >> 3, k8 = (c & 7) * 8;
            uint32_t so = (r * LDT + k8) * 2;
            cp16(s0 + so,         &Bhi[(brow0 + r) * EDIM + kc * 64 + k8]);
            cp16(s0 + B_ARR + so, &Blo[(brow0 + r) * EDIM + kc * 64 + k8]);
        }
        CP_COMMIT();
    };
    prefB(0); prefB(1);

    // ldmatrix base offsets
    uint32_t aOff[2];
    #pragma unroll
    for (int mf = 0; mf < 2; ++mf)
        aOff[mf] = (uint32_t)(((wm + mf * 16 + (lane & 15)) * LDTA + (lane >> 4) * 8) * 2);
    const uint32_t bOff = (uint32_t)(((wn + (lane >> 4) * 8 + (lane & 7)) * LDT
                                      + ((lane >> 3) & 1) * 8) * 2);

    float acc[2][2][4];
    #pragma unroll
    for (int mf = 0; mf < 2; ++mf)
        #pragma unroll
        for (int nf = 0; nf < 2; ++nf)
            #pragma unroll
            for (int j = 0; j < 4; ++j) acc[mf][nf][j] = 0.f;

    for (int it = 0; it < 12; ++it) {
        if (it < 11) CP_WAIT1(); else CP_WAIT0();
        __syncthreads();
        if (it < 10) prefB(it + 2);

        const int kc = it & 3;
        const uint32_t sB = sbase + OFF_B + (uint32_t)(it % 3) * (2 * B_ARR);
        #pragma unroll
        for (int ks = 0; ks < 4; ++ks) {
            const uint32_t aByte = (uint32_t)((kc * 64 + ks * 16) * 2);
            const uint32_t kByte = ks * 32;
            uint32_t ah[2][4], al[2][4], bh[4], bl[4];
            #pragma unroll
            for (int mf = 0; mf < 2; ++mf) {
                ldsm_x4(ah[mf], sbase + OFF_A0 + aOff[mf] + aByte);
                ldsm_x4(al[mf], sbase + OFF_A1 + aOff[mf] + aByte);
            }
            ldsm_x4(bh, sB + bOff + kByte);
            ldsm_x4(bl, sB + B_ARR + bOff + kByte);
            #pragma unroll
            for (int mf = 0; mf < 2; ++mf) {
                #pragma unroll
                for (int nf = 0; nf < 2; ++nf) {
                    mma16816(acc[mf][nf], ah[mf], bh[nf * 2], bh[nf * 2 + 1]);
                    mma16816(acc[mf][nf], ah[mf], bl[nf * 2], bl[nf * 2 + 1]);
                    mma16816(acc[mf][nf], al[mf], bh[nf * 2], bh[nf * 2 + 1]);
                }
            }
        }

        // region boundary epilogues (same thread owns same (s,d) across regions)
        if (kc == 3) {
            const int reg = it >> 2;
            #pragma unroll
            for (int mf = 0; mf < 2; ++mf)
                #pragma unroll
                for (int nf = 0; nf < 2; ++nf)
                    #pragma unroll
                    for (int j = 0; j < 4; ++j) {
                        int s = wm + mf * 16 + (lane >> 2) + (j >> 1) * 8;
                        int d = wn + nf * 8 + (lane & 3) * 2 + (j & 1);
                        float v = acc[mf][nf][j];
                        if (reg == 0)      P[s * 65 + d]  = v * __expf(bq[h * 64 + d]);
                        else if (reg == 1) P[s * 65 + d] *= v * __expf(bk[h * 64 + d]);
                        else               V[s * 68 + d]  = __logf(v) + bv[h * 64 + d];
                        acc[mf][nf][j] = 0.f;
                    }
        }
    }
    __syncthreads();

    // ---- rowsum -> inv -----------------------------------------------------
    if (tid < 64) {
        float s = 0.f;
        #pragma unroll
        for (int j = 0; j < 64; ++j) s += P[tid * 65 + j];
        inv[tid] = 1.0f / s;
    }
    __syncthreads();

    // ---- out = (P * inv) @ V ; EO = exp(out) -------------------------------
    const int tx = tid & 15;
    const int ty = tid >> 4;
    float oacc[4][4] = {};
    #pragma unroll 4
    for (int d = 0; d < 64; ++d) {
        float p0 = P[(4 * ty + 0) * 65 + d];
        float p1 = P[(4 * ty + 1) * 65 + d];
        float p2 = P[(4 * ty + 2) * 65 + d];
        float p3 = P[(4 * ty + 3) * 65 + d];
        float4 v4 = *(const float4*)&V[d * 68 + 4 * tx];
        oacc[0][0] += p0 * v4.x; oacc[0][1] += p0 * v4.y;
        oacc[0][2] += p0 * v4.z; oacc[0][3] += p0 * v4.w;
        oacc[1][0] += p1 * v4.x; oacc[1][1] += p1 * v4.y;
        oacc[1][2] += p1 * v4.z; oacc[1][3] += p1 * v4.w;
        oacc[2][0] += p2 * v4.x; oacc[2][1] += p2 * v4.y;
        oacc[2][2] += p2 * v4.z; oacc[2][3] += p2 * v4.w;
        oacc[3][0] += p3 * v4.x; oacc[3][1] += p3 * v4.y;
        oacc[3][2] += p3 * v4.z; oacc[3][3] += p3 * v4.w;
    }
    #pragma unroll
    for (int r = 0; r < 4; ++r) {
        float iv = inv[4 * ty + r];
        int grow = b * 64 + 4 * ty + r;
        #pragma unroll
        for (int c = 0; c < 4; ++c) {
            float eo = __expf(oacc[r][c] * iv);
            __nv_bfloat16 hb = __float2bfloat16(eo);
            int gi = grow * EDIM + h * 64 + 4 * tx + c;
            g_EOhi[gi] = hb;
            g_EOlo[gi] = __float2bfloat16(eo - __bfloat162float(hb));
        }
    }
}

// ---------------------------------------------------------------------------
// Output projection GEMM (R7 config): out = log(EO @ exp(Wo)) + bo.
//   CTA 64x64, 256 threads, 2-stage cp.async double buffer.
// ---------------------------------------------------------------------------
#define OARR (64 * LDT * 2)                // 9216
#define OSTG (4 * OARR)                    // 36864
#define OSM  (2 * OSTG)                    // 73728

__global__ void __launch_bounds__(256) k_ogemm(
    const __nv_bfloat16* __restrict__ Ahi, const __nv_bfloat16* __restrict__ Alo,
    const __nv_bfloat16* __restrict__ Bhi, const __nv_bfloat16* __restrict__ Blo,
    float* __restrict__ C, const float* __restrict__ b0)
{
    extern __shared__ char smem[];
    const uint32_t sbase = smem_u32(smem);

    const int tid  = threadIdx.x;
    const int lane = tid & 31;
    const int warp = tid >> 5;
    const int wm   = (warp & 1) * 32;
    const int wn   = (warp >> 1) * 16;
    const int m0 = blockIdx.y * 64;
    const int n0 = blockIdx.x * 64;

    uint32_t aOff[2];
    #pragma unroll
    for (int mf = 0; mf < 2; ++mf)
        aOff[mf] = (uint32_t)(((wm + mf * 16 + (lane & 15)) * LDT + (lane >> 4) * 8) * 2);
    const uint32_t bOff = (uint32_t)(((wn + (lane >> 4) * 8 + (lane & 7)) * LDT
                                      + ((lane >> 3) & 1) * 8) * 2);

    float acc[2][2][4];
    #pragma unroll
    for (int mf = 0; mf < 2; ++mf)
        #pragma unroll
        for (int nf = 0; nf < 2; ++nf)
            #pragma unroll
            for (int j = 0; j < 4; ++j) acc[mf][nf][j] = 0.f;

    auto prefetch = [&](int kc, int stg) {
        const int kb = kc * 64;
        const uint32_t s0 = sbase + stg * OSTG;
        #pragma unroll
        for (int i = 0; i < 2; ++i) {
            int c = tid + 256 * i;
            int r = c >> 3, k8 = (c & 7) * 8;
            uint32_t so = (r * LDT + k8) * 2;
            cp16(s0 + 0 * OARR + so, &Ahi[(m0 + r) * EDIM + kb + k8]);
            cp16(s0 + 1 * OARR + so, &Alo[(m0 + r) * EDIM + kb + k8]);
            cp16(s0 + 2 * OARR + so, &Bhi[(n0 + r) * EDIM + kb + k8]);
            cp16(s0 + 3 * OARR + so, &Blo[(n0 + r) * EDIM + kb + k8]);
        }
        CP_COMMIT();
    };

    prefetch(0, 0);

    for (int kc = 0; kc < 4; ++kc) {
        if (kc < 3) prefetch(kc + 1, (kc + 1) & 1);
        if (kc < 3) CP_WAIT1(); else CP_WAIT0();
        __syncthreads();

        const uint32_t s0 = sbase + (kc & 1) * OSTG;
        #pragma unroll
        for (int ks = 0; ks < 4; ++ks) {
            const uint32_t kByte = ks * 32;
            uint32_t ah[2][4], al[2][4], bh[4], bl[4];
            #pragma unroll
            for (int mf = 0; mf < 2; ++mf) {
                ldsm_x4(ah[mf], s0 + 0 * OARR + aOff[mf] + kByte);
                ldsm_x4(al[mf], s0 + 1 * OARR + aOff[mf] + kByte);
            }
            ldsm_x4(bh, s0 + 2 * OARR + bOff + kByte);
            ldsm_x4(bl, s0 + 3 * OARR + bOff + kByte);
            #pragma unroll
            for (int mf = 0; mf < 2; ++mf) {
                #pragma unroll
                for (int nf = 0; nf < 2; ++nf) {
                    mma16816(acc[mf][nf], ah[mf], bh[nf * 2], bh[nf * 2 + 1]);
                    mma16816(acc[mf][nf], ah[mf], bl[nf * 2], bl[nf * 2 + 1]);
                    mma16816(acc[mf][nf], al[mf], bh[nf * 2], bh[nf * 2 + 1]);
                }
            }
        }
        __syncthreads();
    }

    const int l4 = lane >> 2;
    const int l2 = (lane & 3) * 2;
    #pragma unroll
    for (int mf = 0; mf < 2; ++mf) {
        #pragma unroll
        for (int nf = 0; nf < 2; ++nf) {
            int gr = m0 + wm + mf * 16 + l4;
            int gc = n0 + wn + nf * 8 + l2;
            float r[4];
            #pragma unroll
            for (int j = 0; j < 4; ++j)
                r[j] = __logf(acc[mf][nf][j]) + b0[gc + (j & 1)];
            *(float2*)&C[gr * EDIM + gc]       = make_float2(r[0], r[1]);
            *(float2*)&C[(gr + 8) * EDIM + gc] = make_float2(r[2], r[3]);
        }
    }
}

// ---------------------------------------------------------------------------
extern "C" void kernel_launch(void* const* d_in, const int* in_sizes, int n_in,
                              void* d_out, int out_size)
{
    const float* x  = (const float*)d_in[0];
    const float* Wq = (const float*)d_in[1];
    const float* bq = (const float*)d_in[2];
    const float* Wk = (const float*)d_in[3];
    const float* bk = (const float*)d_in[4];
    const float* Wv = (const float*)d_in[5];
    const float* bv = (const float*)d_in[6];
    const float* Wo = (const float*)d_in[7];
    const float* bo = (const float*)d_in[8];
    float* out = (float*)d_out;

    static bool attr_set = false;
    if (!attr_set) {
        cudaFuncSetAttribute(k_qkv_attn, cudaFuncAttributeMaxDynamicSharedMemorySize, FUSED_SMEM);
        cudaFuncSetAttribute(k_ogemm,    cudaFuncAttributeMaxDynamicSharedMemorySize, OSM);
        attr_set = true;
    }

    __nv_bfloat16 *Ahi, *Alo, *Bhi, *Blo, *Chi, *Clo, *EOhi, *EOlo;
    cudaGetSymbolAddress((void**)&Ahi, g_Ahi);
    cudaGetSymbolAddress((void**)&Alo, g_Alo);
    cudaGetSymbolAddress((void**)&Bhi, g_Bhi);
    cudaGetSymbolAddress((void**)&Blo, g_Blo);
    cudaGetSymbolAddress((void**)&Chi, g_Chi);
    cudaGetSymbolAddress((void**)&Clo, g_Clo);
    cudaGetSymbolAddress((void**)&EOhi, g_EOhi);
    cudaGetSymbolAddress((void**)&EOlo, g_EOlo);

    // 1. exp + bf16 hi/lo split of all operands, once
    k_prep<<<768, 256>>>(x, Wq, Wk, Wv, Wo);

    // 2. fused QKV GEMM + attention (128 CTAs, one per (h, b))
    {
        dim3 grid(NH, 32);
        k_qkv_attn<<<grid, 256, FUSED_SMEM>>>(Ahi, Alo, Bhi, Blo, bq, bk, bv);
    }

    // 3. output projection: out = log(EO @ exp(Wo)) + bo
    {
        dim3 grid(EDIM / 64, NROWS / 64);  // (4, 32)
        k_ogemm<<<grid, 256, OSM>>>(EOhi, EOlo, Chi, Clo, out, bo);
    }
}

// round 11
// speedup vs baseline: 1.5148x; 1.0767x over previous
#include <cuda_runtime.h>
#include <cuda_bf16.h>
#include <cstdint>
#include <math.h>

// Problem constants: B=32, S=64, E=256, H=4, D=64
#define NROWS 2048
#define EDIM  256
#define NQKV  768
#define NH    4

// ---------------- scratch (__device__ globals, no allocs) -------------------
__device__ __nv_bfloat16 g_Bhi[NQKV * EDIM],  g_Blo[NQKV * EDIM];    // exp(Wqkv) [n][k]
__device__ __nv_bfloat16 g_Chi[EDIM * EDIM],  g_Clo[EDIM * EDIM];    // exp(Wo)   [n][k]
__device__ __nv_bfloat16 g_EOhi[NROWS * EDIM], g_EOlo[NROWS * EDIM]; // exp(attn out)

// ---------------- helpers (base ISA only — sm_103 non-variant) --------------
__device__ __forceinline__ uint32_t smem_u32(const void* p) {
    uint32_t a;
    asm("{ .reg .u64 t; cvta.to.shared.u64 t, %1; cvt.u32.u64 %0, t; }"
        : "=r"(a) : "l"(p));
    return a;
}
__device__ __forceinline__ void ldsm_x4(uint32_t* r, uint32_t addr) {
    asm volatile("ldmatrix.sync.aligned.m8n8.x4.shared.b16 {%0,%1,%2,%3}, [%4];"
                 : "=r"(r[0]), "=r"(r[1]), "=r"(r[2]), "=r"(r[3]) : "r"(addr));
}
__device__ __forceinline__ void mma16816(float* d, const uint32_t* a,
                                         uint32_t b0, uint32_t b1) {
    asm volatile(
        "mma.sync.aligned.m16n8k16.row.col.f32.bf16.bf16.f32 "
        "{%0,%1,%2,%3}, {%4,%5,%6,%7}, {%8,%9}, {%0,%1,%2,%3};"
        : "+f"(d[0]), "+f"(d[1]), "+f"(d[2]), "+f"(d[3])
        : "r"(a[0]), "r"(a[1]), "r"(a[2]), "r"(a[3]), "r"(b0), "r"(b1));
}
__device__ __forceinline__ void cp16(uint32_t s, const void* g) {
    asm volatile("cp.async.cg.shared.global [%0], [%1], 16;" :: "r"(s), "l"(g));
}
#define CP_COMMIT() asm volatile("cp.async.commit_group;" ::: "memory")
#define CP_WAIT1()  asm volatile("cp.async.wait_group 1;" ::: "memory")
#define CP_WAIT0()  asm volatile("cp.async.wait_group 0;" ::: "memory")

// exp + hi/lo split of 4 floats -> packed bf16x4 (uint2 each)
__device__ __forceinline__ void exp_split4(const float4& v, uint2& hi, uint2& lo) {
    float e[4] = {__expf(v.x), __expf(v.y), __expf(v.z), __expf(v.w)};
    __nv_bfloat16 h[4], l[4];
    #pragma unroll
    for (int j = 0; j < 4; ++j) {
        h[j] = __float2bfloat16(e[j]);
        l[j] = __float2bfloat16(e[j] - __bfloat162float(h[j]));
    }
    __nv_bfloat162 h0 = __halves2bfloat162(h[0], h[1]);
    __nv_bfloat162 h1 = __halves2bfloat162(h[2], h[3]);
    __nv_bfloat162 l0 = __halves2bfloat162(l[0], l[1]);
    __nv_bfloat162 l1 = __halves2bfloat162(l[2], l[3]);
    hi.x = *(uint32_t*)&h0; hi.y = *(uint32_t*)&h1;
    lo.x = *(uint32_t*)&l0; lo.y = *(uint32_t*)&l1;
}

// ---------------------------------------------------------------------------
// Prep: exp + bf16 hi/lo split of the WEIGHTS only (262144 elems / 4 per thr).
// ---------------------------------------------------------------------------
__global__ void k_prep(const float* __restrict__ Wq, const float* __restrict__ Wk,
                       const float* __restrict__ Wv, const float* __restrict__ Wo)
{
    int q = blockIdx.x * blockDim.x + threadIdx.x;   // quad index
    const float* src; __nv_bfloat16 *hi, *lo; int idx;
    if (q < (NQKV * EDIM) / 4) {
        idx = q * 4;
        int n = idx / EDIM, k = idx - n * EDIM;
        const float* W = (n < 256) ? Wq : ((n < 512) ? Wk : Wv);
        src = &W[(n & 255) * EDIM + k]; hi = g_Bhi; lo = g_Blo;
    } else {
        idx = q * 4 - NQKV * EDIM;
        src = &Wo[idx]; hi = g_Chi; lo = g_Clo;
    }
    uint2 h2, l2;
    exp_split4(*(const float4*)src, h2, l2);
    *(uint2*)&hi[idx] = h2;
    *(uint2*)&lo[idx] = l2;
}

// ---------------------------------------------------------------------------
// FUSED exp(x) + QKV GEMM + attention. CTA = (head h, batch b), grid (4, 32).
//   x (64 tokens x 256 fp32) loaded via LDG, exp+split in prolog -> A smem.
//   B streamed: 12 chunks (3 regions q,k,v x 4 k-chunks), 3-stage cp.async.
//   q,k fold into P = q*exp(bq) * k*exp(bk) in smem; v -> V = log(acc)+bv.
//   Then rowsum, attn = P/rowsum, out = attn @ V, EO = exp(out) -> bf16 hi/lo.
// ---------------------------------------------------------------------------
#define LDTA 264                           // A row stride (bf16 elems)
#define A_ARR (64 * LDTA * 2)              // 33792 B
#define LDT 72                             // B row stride
#define B_ARR (64 * LDT * 2)               // 9216 B
#define OFF_A0 0
#define OFF_A1 A_ARR
#define OFF_B  (2 * A_ARR)                 // 67584
#define OFF_P  (OFF_B + 6 * B_ARR)         // 122880
#define OFF_V  (OFF_P + 64 * 65 * 4)       // 139520
#define OFF_INV (OFF_V + 64 * 68 * 4)      // 156928
#define FUSED_SMEM (OFF_INV + 256)         // 157184

__global__ void __launch_bounds__(256) k_qkv_attn(
    const float* __restrict__ x,
    const __nv_bfloat16* __restrict__ Bhi, const __nv_bfloat16* __restrict__ Blo,
    const float* __restrict__ bq, const float* __restrict__ bk,
    const float* __restrict__ bv)
{
    extern __shared__ char smem[];
    const uint32_t sbase = smem_u32(smem);
    float* P   = (float*)(smem + OFF_P);   // [64][65]
    float* V   = (float*)(smem + OFF_V);   // [64][68]
    float* inv = (float*)(smem + OFF_INV);

    const int tid  = threadIdx.x;
    const int lane = tid & 31;
    const int warp = tid >> 5;
    const int wm   = (warp & 1) * 32;
    const int wn   = (warp >> 1) * 16;
    const int h = blockIdx.x;
    const int b = blockIdx.y;
    const int m0 = b * 64;

    // B prefetch: chunk it (region = it>>2, kc = it&3), stage it%3
    auto prefB = [&](int it) {
        const int reg = it >> 2, kc = it & 3;
        const int brow0 = reg * 256 + h * 64;
        const uint32_t s0 = sbase + OFF_B + (uint32_t)(it % 3) * (2 * B_ARR);
        #pragma unroll
        for (int i = 0; i < 2; ++i) {
            int c = tid + 256 * i;
            int r = c >> 3, k8 = (c & 7) * 8;
            uint32_t so = (r * LDT + k8) * 2;
            cp16(s0 + so,         &Bhi[(brow0 + r) * EDIM + kc * 64 + k8]);
            cp16(s0 + B_ARR + so, &Blo[(brow0 + r) * EDIM + kc * 64 + k8]);
        }
        CP_COMMIT();
    };
    prefB(0); prefB(1);

    // ---- prolog: LDG x fp32, exp+split, STS into A hi/lo tiles ------------
    // 2048 8-elem chunks; 8 per thread: r = c>>5, k8 = (c&31)*8
    #pragma unroll
    for (int i = 0; i < 8; ++i) {
        int c = tid + 256 * i;
        int r = c >> 5, k8 = (c & 31) * 8;
        const float4* xs = (const float4*)&x[(m0 + r) * EDIM + k8];
        float4 v0 = xs[0], v1 = xs[1];
        uint2 h0, l0, h1, l1;
        exp_split4(v0, h0, l0);
        exp_split4(v1, h1, l1);
        uint32_t so = (r * LDTA + k8) * 2;
        *(uint4*)(smem + OFF_A0 + so) = make_uint4(h0.x, h0.y, h1.x, h1.y);
        *(uint4*)(smem + OFF_A1 + so) = make_uint4(l0.x, l0.y, l1.x, l1.y);
    }

    // ldmatrix base offsets
    uint32_t aOff[2];
    #pragma unroll
    for (int mf = 0; mf < 2; ++mf)
        aOff[mf] = (uint32_t)(((wm + mf * 16 + (lane & 15)) * LDTA + (lane >> 4) * 8) * 2);
    const uint32_t bOff = (uint32_t)(((wn + (lane >> 4) * 8 + (lane & 7)) * LDT
                                      + ((lane >> 3) & 1) * 8) * 2);

    float acc[2][2][4];
    #pragma unroll
    for (int mf = 0; mf < 2; ++mf)
        #pragma unroll
        for (int nf = 0; nf < 2; ++nf)
            #pragma unroll
            for (int j = 0; j < 4; ++j) acc[mf][nf][j] = 0.f;

    for (int it = 0; it < 12; ++it) {
        if (it < 11) CP_WAIT1(); else CP_WAIT0();
        __syncthreads();                 // publishes A STS (it==0) + B chunk it
        if (it < 10) prefB(it + 2);

        const int kc = it & 3;
        const uint32_t sB = sbase + OFF_B + (uint32_t)(it % 3) * (2 * B_ARR);
        #pragma unroll
        for (int ks = 0; ks < 4; ++ks) {
            const uint32_t aByte = (uint32_t)((kc * 64 + ks * 16) * 2);
            const uint32_t kByte = ks * 32;
            uint32_t ah[2][4], al[2][4], bh[4], bl[4];
            #pragma unroll
            for (int mf = 0; mf < 2; ++mf) {
                ldsm_x4(ah[mf], sbase + OFF_A0 + aOff[mf] + aByte);
                ldsm_x4(al[mf], sbase + OFF_A1 + aOff[mf] + aByte);
            }
            ldsm_x4(bh, sB + bOff + kByte);
            ldsm_x4(bl, sB + B_ARR + bOff + kByte);
            #pragma unroll
            for (int mf = 0; mf < 2; ++mf) {
                #pragma unroll
                for (int nf = 0; nf < 2; ++nf) {
                    mma16816(acc[mf][nf], ah[mf], bh[nf * 2], bh[nf * 2 + 1]);
                    mma16816(acc[mf][nf], ah[mf], bl[nf * 2], bl[nf * 2 + 1]);
                    mma16816(acc[mf][nf], al[mf], bh[nf * 2], bh[nf * 2 + 1]);
                }
            }
        }

        // region boundary epilogues (same thread owns same (s,d) across regions)
        if (kc == 3) {
            const int reg = it >> 2;
            #pragma unroll
            for (int mf = 0; mf < 2; ++mf)
                #pragma unroll
                for (int nf = 0; nf < 2; ++nf)
                    #pragma unroll
                    for (int j = 0; j < 4; ++j) {
                        int s = wm + mf * 16 + (lane >> 2) + (j >> 1) * 8;
                        int d = wn + nf * 8 + (lane & 3) * 2 + (j & 1);
                        float v = acc[mf][nf][j];
                        if (reg == 0)      P[s * 65 + d]  = v * __expf(bq[h * 64 + d]);
                        else if (reg == 1) P[s * 65 + d] *= v * __expf(bk[h * 64 + d]);
                        else               V[s * 68 + d]  = __logf(v) + bv[h * 64 + d];
                        acc[mf][nf][j] = 0.f;
                    }
        }
    }
    __syncthreads();

    // ---- rowsum -> inv -----------------------------------------------------
    if (tid < 64) {
        float s = 0.f;
        #pragma unroll
        for (int j = 0; j < 64; ++j) s += P[tid * 65 + j];
        inv[tid] = 1.0f / s;
    }
    __syncthreads();

    // ---- out = (P * inv) @ V ; EO = exp(out) -------------------------------
    const int tx = tid & 15;
    const int ty = tid >> 4;
    float oacc[4][4] = {};
    #pragma unroll 4
    for (int d = 0; d < 64; ++d) {
        float p0 = P[(4 * ty + 0) * 65 + d];
        float p1 = P[(4 * ty + 1) * 65 + d];
        float p2 = P[(4 * ty + 2) * 65 + d];
        float p3 = P[(4 * ty + 3) * 65 + d];
        float4 v4 = *(const float4*)&V[d * 68 + 4 * tx];
        oacc[0][0] += p0 * v4.x; oacc[0][1] += p0 * v4.y;
        oacc[0][2] += p0 * v4.z; oacc[0][3] += p0 * v4.w;
        oacc[1][0] += p1 * v4.x; oacc[1][1] += p1 * v4.y;
        oacc[1][2] += p1 * v4.z; oacc[1][3] += p1 * v4.w;
        oacc[2][0] += p2 * v4.x; oacc[2][1] += p2 * v4.y;
        oacc[2][2] += p2 * v4.z; oacc[2][3] += p2 * v4.w;
        oacc[3][0] += p3 * v4.x; oacc[3][1] += p3 * v4.y;
        oacc[3][2] += p3 * v4.z; oacc[3][3] += p3 * v4.w;
    }
    #pragma unroll
    for (int r = 0; r < 4; ++r) {
        float iv = inv[4 * ty + r];
        int grow = b * 64 + 4 * ty + r;
        #pragma unroll
        for (int c = 0; c < 4; ++c) {
            float eo = __expf(oacc[r][c] * iv);
            __nv_bfloat16 hb = __float2bfloat16(eo);
            int gi = grow * EDIM + h * 64 + 4 * tx + c;
            g_EOhi[gi] = hb;
            g_EOlo[gi] = __float2bfloat16(eo - __bfloat162float(hb));
        }
    }
}

// ---------------------------------------------------------------------------
// Output projection GEMM: out = log(EO @ exp(Wo)) + bo.
//   CTA 64x64, 256 threads, 2-stage cp.async double buffer.
// ---------------------------------------------------------------------------
#define OARR (64 * LDT * 2)                // 9216
#define OSTG (4 * OARR)                    // 36864
#define OSM  (2 * OSTG)                    // 73728

__global__ void __launch_bounds__(256) k_ogemm(
    const __nv_bfloat16* __restrict__ Ahi, const __nv_bfloat16* __restrict__ Alo,
    const __nv_bfloat16* __restrict__ Bhi, const __nv_bfloat16* __restrict__ Blo,
    float* __restrict__ C, const float* __restrict__ b0)
{
    extern __shared__ char smem[];
    const uint32_t sbase = smem_u32(smem);

    const int tid  = threadIdx.x;
    const int lane = tid & 31;
    const int warp = tid >> 5;
    const int wm   = (warp & 1) * 32;
    const int wn   = (warp >> 1) * 16;
    const int m0 = blockIdx.y * 64;
    const int n0 = blockIdx.x * 64;

    uint32_t aOff[2];
    #pragma unroll
    for (int mf = 0; mf < 2; ++mf)
        aOff[mf] = (uint32_t)(((wm + mf * 16 + (lane & 15)) * LDT + (lane >> 4) * 8) * 2);
    const uint32_t bOff = (uint32_t)(((wn + (lane >> 4) * 8 + (lane & 7)) * LDT
                                      + ((lane >> 3) & 1) * 8) * 2);

    float acc[2][2][4];
    #pragma unroll
    for (int mf = 0; mf < 2; ++mf)
        #pragma unroll
        for (int nf = 0; nf < 2; ++nf)
            #pragma unroll
            for (int j = 0; j < 4; ++j) acc[mf][nf][j] = 0.f;

    auto prefetch = [&](int kc, int stg) {
        const int kb = kc * 64;
        const uint32_t s0 = sbase + stg * OSTG;
        #pragma unroll
        for (int i = 0; i < 2; ++i) {
            int c = tid + 256 * i;
            int r = c >> 3, k8 = (c & 7) * 8;
            uint32_t so = (r * LDT + k8) * 2;
            cp16(s0 + 0 * OARR + so, &Ahi[(m0 + r) * EDIM + kb + k8]);
            cp16(s0 + 1 * OARR + so, &Alo[(m0 + r) * EDIM + kb + k8]);
            cp16(s0 + 2 * OARR + so, &Bhi[(n0 + r) * EDIM + kb + k8]);
            cp16(s0 + 3 * OARR + so, &Blo[(n0 + r) * EDIM + kb + k8]);
        }
        CP_COMMIT();
    };

    prefetch(0, 0);

    for (int kc = 0; kc < 4; ++kc) {
        if (kc < 3) prefetch(kc + 1, (kc + 1) & 1);
        if (kc < 3) CP_WAIT1(); else CP_WAIT0();
        __syncthreads();

        const uint32_t s0 = sbase + (kc & 1) * OSTG;
        #pragma unroll
        for (int ks = 0; ks < 4; ++ks) {
            const uint32_t kByte = ks * 32;
            uint32_t ah[2][4], al[2][4], bh[4], bl[4];
            #pragma unroll
            for (int mf = 0; mf < 2; ++mf) {
                ldsm_x4(ah[mf], s0 + 0 * OARR + aOff[mf] + kByte);
                ldsm_x4(al[mf], s0 + 1 * OARR + aOff[mf] + kByte);
            }
            ldsm_x4(bh, s0 + 2 * OARR + bOff + kByte);
            ldsm_x4(bl, s0 + 3 * OARR + bOff + kByte);
            #pragma unroll
            for (int mf = 0; mf < 2; ++mf) {
                #pragma unroll
                for (int nf = 0; nf < 2; ++nf) {
                    mma16816(acc[mf][nf], ah[mf], bh[nf * 2], bh[nf * 2 + 1]);
                    mma16816(acc[mf][nf], ah[mf], bl[nf * 2], bl[nf * 2 + 1]);
                    mma16816(acc[mf][nf], al[mf], bh[nf * 2], bh[nf * 2 + 1]);
                }
            }
        }
        __syncthreads();
    }

    const int l4 = lane >> 2;
    const int l2 = (lane & 3) * 2;
    #pragma unroll
    for (int mf = 0; mf < 2; ++mf) {
        #pragma unroll
        for (int nf = 0; nf < 2; ++nf) {
            int gr = m0 + wm + mf * 16 + l4;
            int gc = n0 + wn + nf * 8 + l2;
            float r[4];
            #pragma unroll
            for (int j = 0; j < 4; ++j)
                r[j] = __logf(acc[mf][nf][j]) + b0[gc + (j & 1)];
            *(float2*)&C[gr * EDIM + gc]       = make_float2(r[0], r[1]);
            *(float2*)&C[(gr + 8) * EDIM + gc] = make_float2(r[2], r[3]);
        }
    }
}

// ---------------------------------------------------------------------------
extern "C" void kernel_launch(void* const* d_in, const int* in_sizes, int n_in,
                              void* d_out, int out_size)
{
    const float* x  = (const float*)d_in[0];
    const float* Wq = (const float*)d_in[1];
    const float* bq = (const float*)d_in[2];
    const float* Wk = (const float*)d_in[3];
    const float* bk = (const float*)d_in[4];
    const float* Wv = (const float*)d_in[5];
    const float* bv = (const float*)d_in[6];
    const float* Wo = (const float*)d_in[7];
    const float* bo = (const float*)d_in[8];
    float* out = (float*)d_out;

    static bool attr_set = false;
    if (!attr_set) {
        cudaFuncSetAttribute(k_qkv_attn, cudaFuncAttributeMaxDynamicSharedMemorySize, FUSED_SMEM);
        cudaFuncSetAttribute(k_ogemm,    cudaFuncAttributeMaxDynamicSharedMemorySize, OSM);
        attr_set = true;
    }

    __nv_bfloat16 *Bhi, *Blo, *Chi, *Clo, *EOhi, *EOlo;
    cudaGetSymbolAddress((void**)&Bhi, g_Bhi);
    cudaGetSymbolAddress((void**)&Blo, g_Blo);
    cudaGetSymbolAddress((void**)&Chi, g_Chi);
    cudaGetSymbolAddress((void**)&Clo, g_Clo);
    cudaGetSymbolAddress((void**)&EOhi, g_EOhi);
    cudaGetSymbolAddress((void**)&EOlo, g_EOlo);

    // 1. exp + bf16 hi/lo split of the weights only (262144 elems / 4)
    k_prep<<<256, 256>>>(Wq, Wk, Wv, Wo);

    // 2. fused exp(x) + QKV GEMM + attention (128 CTAs, one per (h, b))
    {
        dim3 grid(NH, 32);
        k_qkv_attn<<<grid, 256, FUSED_SMEM>>>(x, Bhi, Blo, bq, bk, bv);
    }

    // 3. output projection: out = log(EO @ exp(Wo)) + bo
    {
        dim3 grid(EDIM / 64, NROWS / 64);  // (4, 32)
        k_ogemm<<<grid, 256, OSM>>>(EOhi, EOlo, Chi, Clo, out, bo);
    }
}